// round 12
// baseline (speedup 1.0000x reference)
#include <cuda_runtime.h>
#include <cuda_bf16.h>
#include <cstdint>

// out[i] = softmax((x2[i] @ v1^T)/1000) @ x2[i],  v1 = x1@W.T + b,  N=384.
// P = 1/384 + delta  ->  out = colsum(x2[i])/384 + delta @ x2[i].
// GEMMs: mma.sync m16n8k16 bf16. ALL operands (except delta) prebaked in gmem as
// ldmatrix-equivalent register fragments: one uint4 per (16x16 tile, lane), so the
// attention mainloop is pure LDG.128 + MMA with NO smem staging and NO barriers.

constexpr int N = 384;
constexpr float SCALE_INV = 1.0f / 1000.0f;
constexpr float INV_N = 1.0f / 384.0f;

constexpr int QS = 392;   // delta smem row stride (halves): 384 + 8 pad

constexpr int OFF_SROW = 128 * QS * 2;                 // 100352
constexpr int OFF_CS   = OFF_SROW + 512 * 4;           // 102400
constexpr int SMEM_ATTN = OFF_CS + 384 * 4;            // 103936

// Fragment images. Layouts (uint4 = {w0,w1,w2,w3} = the 4 regs ldmatrix would return):
//  A-frag (Q):  a0=(m-lo,k-lo) a1=(m-hi,k-lo) a2=(m-lo,k-hi) a3=(m-hi,k-hi)
//  B-frag (v1): b0=(n-lo,k-lo) b1=(n-lo,k-hi) b2=(n-hi,k-lo) b3=(n-hi,k-hi)
//  B-frag (V,trans): w0=(k-lo,c-lo) w1=(k-hi,c-lo) w2=(k-lo,c-hi) w3=(k-hi,c-hi)
__device__ uint4 g_qf[(size_t)384 * 3 * 24 * 8 * 32];   // [i][jb][kc][mt][lane]
__device__ uint4 g_vf[(size_t)384 * 24 * 24 * 32];      // [i][nc][ct][lane]
__device__ uint4 g_v1f[24 * 24 * 32];                   // [kc][nb][lane]
__device__ float g_cs24[(size_t)384 * 24 * 384];        // 16-row colsum partials

// ---------------------------------------------------------------------------
__device__ __forceinline__ uint32_t smem_u32(const void* p) {
    uint32_t a;
    asm("{ .reg .u64 t; cvta.to.shared.u64 t, %1; cvt.u32.u64 %0, t; }" : "=r"(a) : "l"(p));
    return a;
}
__device__ __forceinline__ void ldm4(uint32_t* r, uint32_t addr) {
    asm volatile("ldmatrix.sync.aligned.m8n8.x4.shared.b16 {%0,%1,%2,%3},[%4];"
                 : "=r"(r[0]), "=r"(r[1]), "=r"(r[2]), "=r"(r[3]) : "r"(addr));
}
__device__ __forceinline__ void mma16816(float* d, const uint32_t* a, uint32_t b0, uint32_t b1) {
    asm volatile("mma.sync.aligned.m16n8k16.row.col.f32.bf16.bf16.f32 "
                 "{%0,%1,%2,%3},{%4,%5,%6,%7},{%8,%9},{%0,%1,%2,%3};"
                 : "+f"(d[0]), "+f"(d[1]), "+f"(d[2]), "+f"(d[3])
                 : "r"(a[0]), "r"(a[1]), "r"(a[2]), "r"(a[3]), "r"(b0), "r"(b1));
}
__device__ __forceinline__ uint32_t bf2_pack(float a, float b) {
    __nv_bfloat162 h = __floats2bfloat162_rn(a, b);
    return *reinterpret_cast<uint32_t*>(&h);
}

// ---------------------------------------------------------------------------
// prep kernel, grid (24, 385), 256 threads:
//   by < 384 : batch i=by, 16-row group g=bx -> q-frags, v-frags, colsum partial
//   by == 384: bx < 12 -> linear slab L=bx (32 n-rows of v1) -> v1-frags
// ---------------------------------------------------------------------------
constexpr int SMEM_PREP = 32 * 388 * 4;   // 49664 (covers both branches)

__global__ __launch_bounds__(256) void prep_kernel(const float* __restrict__ x1,
                                                   const float* __restrict__ W,
                                                   const float* __restrict__ b,
                                                   const float* __restrict__ x2) {
    extern __shared__ float dsf[];
    const int tid = threadIdx.x;
    const int lane = tid & 31;
    const int warp = tid >> 5;
    const int bx = blockIdx.x, by = blockIdx.y;

    if (by == 384) {
        if (bx >= 12) return;
        // ------------- linear: v1[n][k] = sum_m x1[n][m]*W[k][m] + b[k] -------------
        float* sX = dsf;                // [32][17]
        float* sW = dsf + 32 * 17;      // [384][17]
        const int L = bx;
        const int n0 = L * 32;
        const int nl = (tid & 15) * 2;
        const int k0 = (tid >> 4) * 24;
        float acc[2][24];
#pragma unroll
        for (int r = 0; r < 2; ++r)
#pragma unroll
            for (int j = 0; j < 24; ++j) acc[r][j] = 0.0f;

        for (int m0 = 0; m0 < N; m0 += 16) {
#pragma unroll
            for (int q = 0; q < 2; ++q) {
                int idx = tid + q * 256;
                int n = idx >> 4, m = idx & 15;
                sX[n * 17 + m] = x1[(size_t)(n0 + n) * N + m0 + m];
            }
#pragma unroll
            for (int q = 0; q < 24; ++q) {
                int idx = tid + q * 256;
                int k = idx >> 4, m = idx & 15;
                sW[k * 17 + m] = W[(size_t)k * N + m0 + m];
            }
            __syncthreads();
#pragma unroll
            for (int mm = 0; mm < 16; ++mm) {
                float x0 = sX[nl * 17 + mm];
                float x1v = sX[(nl + 1) * 17 + mm];
#pragma unroll
                for (int j = 0; j < 24; ++j) {
                    float w = sW[(k0 + j) * 17 + mm];
                    acc[0][j] += x0 * w;
                    acc[1][j] += x1v * w;
                }
            }
            __syncthreads();
        }
        // stage v1 tile (32 x 384 fp32) into dsf (aliases sX/sW; reads are done)
        float* sv = dsf;                // [32][388]
#pragma unroll
        for (int r = 0; r < 2; ++r)
#pragma unroll
            for (int j = 0; j < 24; ++j)
                sv[(nl + r) * 388 + k0 + j] = acc[r][j] + __ldg(b + k0 + j);
        __syncthreads();
        // write B fragments: 48 tiles (2 n-blocks x 24 kc), 6 per warp
#pragma unroll
        for (int t = warp * 6; t < warp * 6 + 6; ++t) {
            int kc = t % 24, nbl = t / 24;
            int kb = kc * 16, nb = nbl * 16;
            int r0 = lane >> 2, c0 = 2 * (lane & 3);
            uint32_t w0 = bf2_pack(sv[(nb + r0) * 388 + kb + c0],     sv[(nb + r0) * 388 + kb + c0 + 1]);
            uint32_t w1 = bf2_pack(sv[(nb + r0) * 388 + kb + 8 + c0], sv[(nb + r0) * 388 + kb + 9 + c0]);
            uint32_t w2 = bf2_pack(sv[(nb + 8 + r0) * 388 + kb + c0],     sv[(nb + 8 + r0) * 388 + kb + c0 + 1]);
            uint32_t w3 = bf2_pack(sv[(nb + 8 + r0) * 388 + kb + 8 + c0], sv[(nb + 8 + r0) * 388 + kb + 9 + c0]);
            g_v1f[((size_t)kc * 24 + L * 2 + nbl) * 32 + lane] = make_uint4(w0, w1, w2, w3);
        }
        return;
    }

    // ------------- fragment images for x2: batch i, 16-row group g -------------
    const int i = by, g = bx;
    float* sm = dsf;                     // [16][388]
    const float* src = x2 + ((size_t)i * N + g * 16) * N;
#pragma unroll
    for (int q = 0; q < 6; ++q) {
        int idx = tid + q * 256;          // 1536 float4
        int row = idx / 96, c4 = idx % 96;
        float4 f = __ldg(reinterpret_cast<const float4*>(src + (size_t)row * N) + c4);
        *reinterpret_cast<float4*>(sm + row * 388 + c4 * 4) = f;
    }
    __syncthreads();

    const int jb = g >> 3, mt = g & 7;
    const int r0 = lane >> 2, c0 = 2 * (lane & 3);
    // A-fragments (Q rows g*16..+16): warp handles 3 kc
#pragma unroll
    for (int t = 0; t < 3; ++t) {
        int kc = warp * 3 + t;
        int kb = kc * 16;
        uint32_t w0 = bf2_pack(sm[r0 * 388 + kb + c0],           sm[r0 * 388 + kb + c0 + 1]);
        uint32_t w1 = bf2_pack(sm[(r0 + 8) * 388 + kb + c0],     sm[(r0 + 8) * 388 + kb + c0 + 1]);
        uint32_t w2 = bf2_pack(sm[r0 * 388 + kb + 8 + c0],       sm[r0 * 388 + kb + 9 + c0]);
        uint32_t w3 = bf2_pack(sm[(r0 + 8) * 388 + kb + 8 + c0], sm[(r0 + 8) * 388 + kb + 9 + c0]);
        g_qf[((((size_t)i * 3 + jb) * 24 + kc) * 8 + mt) * 32 + lane] = make_uint4(w0, w1, w2, w3);
    }
    // B-fragments (V chunk nc=g, trans layout): warp handles 3 ct
    const int kq = 2 * (lane & 3), cp = lane >> 2;
#pragma unroll
    for (int t = 0; t < 3; ++t) {
        int ct = warp * 3 + t;
        int cb = ct * 16;
        uint32_t w0 = bf2_pack(sm[kq * 388 + cb + cp],           sm[(kq + 1) * 388 + cb + cp]);
        uint32_t w1 = bf2_pack(sm[(kq + 8) * 388 + cb + cp],     sm[(kq + 9) * 388 + cb + cp]);
        uint32_t w2 = bf2_pack(sm[kq * 388 + cb + 8 + cp],       sm[(kq + 1) * 388 + cb + 8 + cp]);
        uint32_t w3 = bf2_pack(sm[(kq + 8) * 388 + cb + 8 + cp], sm[(kq + 9) * 388 + cb + 8 + cp]);
        g_vf[(((size_t)i * 24 + g) * 24 + ct) * 32 + lane] = make_uint4(w0, w1, w2, w3);
    }
    // colsum partial over these 16 rows
    for (int c = tid; c < 384; c += 256) {
        float s = 0.f;
#pragma unroll
        for (int r = 0; r < 16; ++r) s += sm[r * 388 + c];
        g_cs24[((size_t)i * 24 + g) * 384 + c] = s;
    }
}

// ---------------------------------------------------------------------------
// Fused attention: 512 threads, 16 warps = 4 row x 4 col groups.
// Mainloops: pure LDG.128 fragments + MMA. No smem staging, no mainloop barriers.
// ---------------------------------------------------------------------------
__global__ __launch_bounds__(512, 1)
void attn_kernel(float* __restrict__ out) {
    extern __shared__ char smem[];
    __nv_bfloat16* sD = reinterpret_cast<__nv_bfloat16*>(smem);   // delta (GEMM2 A)
    float* srow = reinterpret_cast<float*>(smem + OFF_SROW);
    float* cs_s = reinterpret_cast<float*>(smem + OFF_CS);

    const int tid = threadIdx.x;
    const int lane = tid & 31;
    const int warp = tid >> 5;
    const int wr = warp & 3;       // rows wr*32..+32
    const int wc = warp >> 2;      // cols wc*96..+96
    const int i = blockIdx.y;
    const int jb = blockIdx.x;
    const int j0 = jb * 128;

    const uint32_t sDu = smem_u32(smem);
    const int rowA = (lane & 7) + ((lane >> 3) & 1) * 8;
    const int colA = (lane >> 4) * 8;
    const uint32_t aBase = sDu + ((wr * 32 + rowA) * QS + colA) * 2;

    float acc[2][12][4];
#pragma unroll
    for (int ma = 0; ma < 2; ++ma)
#pragma unroll
        for (int na = 0; na < 12; ++na)
#pragma unroll
            for (int r = 0; r < 4; ++r) acc[ma][na][r] = 0.0f;

    // =================== GEMM1: S = Q @ v1^T (fragments from gmem) ===================
    const uint4* qf = g_qf + ((size_t)i * 3 + jb) * 24 * 8 * 32;
#pragma unroll 2
    for (int kc = 0; kc < 24; ++kc) {
        uint4 af0 = __ldg(qf + (kc * 8 + wr * 2) * 32 + lane);
        uint4 af1 = __ldg(qf + (kc * 8 + wr * 2 + 1) * 32 + lane);
        const uint32_t* a0 = reinterpret_cast<const uint32_t*>(&af0);
        const uint32_t* a1 = reinterpret_cast<const uint32_t*>(&af1);
#pragma unroll
        for (int nbx = 0; nbx < 6; ++nbx) {
            uint4 bf = __ldg(g_v1f + (kc * 24 + wc * 6 + nbx) * 32 + lane);
            mma16816(acc[0][2 * nbx],     a0, bf.x, bf.y);
            mma16816(acc[0][2 * nbx + 1], a0, bf.z, bf.w);
            mma16816(acc[1][2 * nbx],     a1, bf.x, bf.y);
            mma16816(acc[1][2 * nbx + 1], a1, bf.z, bf.w);
        }
    }

    // ---- colsum -> smem (24 partials) ----
    if (tid < 384) {
        float s = 0.f;
#pragma unroll
        for (int p = 0; p < 24; ++p)
            s += __ldg(g_cs24 + ((size_t)i * 24 + p) * 384 + tid);
        cs_s[tid] = s;
    }

    // =================== softmax: delta = e/s - 1/N (bf16 into sD) ===================
    float rs[2][2] = {{0.f, 0.f}, {0.f, 0.f}};
#pragma unroll
    for (int ma = 0; ma < 2; ++ma)
#pragma unroll
        for (int na = 0; na < 12; ++na) {
            float* d = acc[ma][na];
            d[0] = __expf(d[0] * SCALE_INV);
            d[1] = __expf(d[1] * SCALE_INV);
            d[2] = __expf(d[2] * SCALE_INV);
            d[3] = __expf(d[3] * SCALE_INV);
            rs[ma][0] += d[0] + d[1];
            rs[ma][1] += d[2] + d[3];
        }
#pragma unroll
    for (int ma = 0; ma < 2; ++ma)
#pragma unroll
        for (int h = 0; h < 2; ++h) {
            rs[ma][h] += __shfl_xor_sync(0xffffffffu, rs[ma][h], 1);
            rs[ma][h] += __shfl_xor_sync(0xffffffffu, rs[ma][h], 2);
        }
    if ((lane & 3) == 0) {
#pragma unroll
        for (int ma = 0; ma < 2; ++ma)
#pragma unroll
            for (int h = 0; h < 2; ++h)
                srow[wc * 128 + wr * 32 + ma * 16 + h * 8 + (lane >> 2)] = rs[ma][h];
    }
    __syncthreads();
    float invs[2][2];
#pragma unroll
    for (int ma = 0; ma < 2; ++ma)
#pragma unroll
        for (int h = 0; h < 2; ++h) {
            int r = wr * 32 + ma * 16 + h * 8 + (lane >> 2);
            invs[ma][h] = 1.0f / (srow[r] + srow[128 + r] + srow[256 + r] + srow[384 + r]);
        }
#pragma unroll
    for (int ma = 0; ma < 2; ++ma)
#pragma unroll
        for (int na = 0; na < 12; ++na) {
            int r = wr * 32 + ma * 16 + (lane >> 2);
            int c = wc * 96 + (na >> 1) * 16 + (na & 1) * 8 + (lane & 3) * 2;
            float* d = acc[ma][na];
            *reinterpret_cast<uint32_t*>(sD + r * QS + c) =
                bf2_pack(d[0] * invs[ma][0] - INV_N, d[1] * invs[ma][0] - INV_N);
            *reinterpret_cast<uint32_t*>(sD + (r + 8) * QS + c) =
                bf2_pack(d[2] * invs[ma][1] - INV_N, d[3] * invs[ma][1] - INV_N);
        }
    __syncthreads();

    // =================== GEMM2: corr = delta @ V (B fragments from gmem) ===================
#pragma unroll
    for (int ma = 0; ma < 2; ++ma)
#pragma unroll
        for (int na = 0; na < 12; ++na)
#pragma unroll
            for (int r = 0; r < 4; ++r) acc[ma][na][r] = 0.0f;

    const uint4* vf = g_vf + (size_t)i * 24 * 24 * 32;
#pragma unroll 2
    for (int nc = 0; nc < 24; ++nc) {
        uint32_t a[2][4];
#pragma unroll
        for (int ma = 0; ma < 2; ++ma)
            ldm4(a[ma], aBase + (ma * 16 * QS + nc * 16) * 2);
#pragma unroll
        for (int nbx = 0; nbx < 6; ++nbx) {
            uint4 bf = __ldg(vf + (nc * 24 + wc * 6 + nbx) * 32 + lane);
            mma16816(acc[0][2 * nbx],     a[0], bf.x, bf.y);
            mma16816(acc[0][2 * nbx + 1], a[0], bf.z, bf.w);
            mma16816(acc[1][2 * nbx],     a[1], bf.x, bf.y);
            mma16816(acc[1][2 * nbx + 1], a[1], bf.z, bf.w);
        }
    }

    // =================== epilogue: out = corr + colsum/384 ===================
#pragma unroll
    for (int ma = 0; ma < 2; ++ma)
#pragma unroll
        for (int nbx = 0; nbx < 6; ++nbx)
#pragma unroll
            for (int ct = 0; ct < 2; ++ct) {
                int na = nbx * 2 + ct;
                int r = j0 + wr * 32 + ma * 16 + (lane >> 2);
                int c = wc * 96 + nbx * 16 + ct * 8 + (lane & 3) * 2;
                float cs0 = cs_s[c] * INV_N;
                float cs1 = cs_s[c + 1] * INV_N;
                float* d = acc[ma][na];
                float2 o0 = make_float2(d[0] + cs0, d[1] + cs1);
                float2 o1 = make_float2(d[2] + cs0, d[3] + cs1);
                *reinterpret_cast<float2*>(out + ((size_t)i * N + r) * N + c) = o0;
                *reinterpret_cast<float2*>(out + ((size_t)i * N + r + 8) * N + c) = o1;
            }
}

// ---------------------------------------------------------------------------
extern "C" void kernel_launch(void* const* d_in, const int* in_sizes, int n_in,
                              void* d_out, int out_size) {
    const float* x1 = (const float*)d_in[0];
    const float* x2 = (const float*)d_in[1];
    const float* W  = (const float*)d_in[2];
    const float* b  = (const float*)d_in[3];
    float* out = (float*)d_out;
    (void)in_sizes; (void)n_in; (void)out_size;

    {
        cudaFuncSetAttribute(prep_kernel, cudaFuncAttributeMaxDynamicSharedMemorySize, SMEM_PREP);
        dim3 g(24, 385);
        prep_kernel<<<g, 256, SMEM_PREP>>>(x1, W, b, x2);
    }
    {
        cudaFuncSetAttribute(attn_kernel, cudaFuncAttributeMaxDynamicSharedMemorySize, SMEM_ATTN);
        dim3 g(3, 384);
        attn_kernel<<<g, 512, SMEM_ATTN>>>(out);
    }
}

// round 13
// speedup vs baseline: 1.9197x; 1.9197x over previous
#include <cuda_runtime.h>
#include <cuda_bf16.h>
#include <cstdint>

// out[i] = softmax((x2[i] @ v1^T)/1000) @ x2[i],  v1 = x1@W.T + b,  N=384.
// P = 1/384 + delta  ->  out = colsum(x2[i])/384 + delta @ x2[i].
// GEMMs: mma.sync m16n8k16 bf16, prebaked bf16 operands (R11 geometry).
// R13: 2 chunks per synchronization (4 buffers, wait_group 0), halving barrier count.

constexpr int N = 384;
constexpr float SCALE_INV = 1.0f / 1000.0f;
constexpr float INV_N = 1.0f / 384.0f;

constexpr int QS = 392;   // sQ row stride (halves): 384 + 8 pad
constexpr int BS = 24;    // GEMM1 B row stride (halves): 16 + 8 pad
constexpr int VS = 392;   // GEMM2 B row stride (halves)

constexpr int SQ_BYTES = 128 * QS * 2;        // 100352
constexpr int BUF_B    = 18432;               // max(384*BS*2, 16*VS*2)
constexpr int OFF_BUF  = SQ_BYTES;
constexpr int OFF_SROW = OFF_BUF + 4 * BUF_B;            // 174080
constexpr int OFF_CS   = OFF_SROW + 512 * 4;             // 176128
constexpr int SMEM_ATTN = OFF_CS + 384 * 4;              // 177664

__device__ __align__(16) __nv_bfloat16 g_v1b[N * N];                 // v1[n][k] bf16
__device__ __align__(16) __nv_bfloat16 g_x2b[(size_t)N * N * N];     // x2 bf16 image
__device__ float g_cs6[(size_t)N * 6 * N];                           // partial colsums

// ---------------------------------------------------------------------------
__device__ __forceinline__ uint32_t smem_u32(const void* p) {
    uint32_t a;
    asm("{ .reg .u64 t; cvta.to.shared.u64 t, %1; cvt.u32.u64 %0, t; }" : "=r"(a) : "l"(p));
    return a;
}
__device__ __forceinline__ void ldm4(uint32_t* r, uint32_t addr) {
    asm volatile("ldmatrix.sync.aligned.m8n8.x4.shared.b16 {%0,%1,%2,%3},[%4];"
                 : "=r"(r[0]), "=r"(r[1]), "=r"(r[2]), "=r"(r[3]) : "r"(addr));
}
__device__ __forceinline__ void ldm4t(uint32_t* r, uint32_t addr) {
    asm volatile("ldmatrix.sync.aligned.m8n8.x4.trans.shared.b16 {%0,%1,%2,%3},[%4];"
                 : "=r"(r[0]), "=r"(r[1]), "=r"(r[2]), "=r"(r[3]) : "r"(addr));
}
__device__ __forceinline__ void mma16816(float* d, const uint32_t* a, uint32_t b0, uint32_t b1) {
    asm volatile("mma.sync.aligned.m16n8k16.row.col.f32.bf16.bf16.f32 "
                 "{%0,%1,%2,%3},{%4,%5,%6,%7},{%8,%9},{%0,%1,%2,%3};"
                 : "+f"(d[0]), "+f"(d[1]), "+f"(d[2]), "+f"(d[3])
                 : "r"(a[0]), "r"(a[1]), "r"(a[2]), "r"(a[3]), "r"(b0), "r"(b1));
}
__device__ __forceinline__ uint32_t bf2_pack(float a, float b) {
    __nv_bfloat162 h = __floats2bfloat162_rn(a, b);
    return *reinterpret_cast<uint32_t*>(&h);
}
__device__ __forceinline__ void cp16(uint32_t dst, const void* src) {
    asm volatile("cp.async.cg.shared.global [%0], [%1], 16;" :: "r"(dst), "l"(src));
}
#define CP_COMMIT() asm volatile("cp.async.commit_group;" ::: "memory")
#define CP_WAIT0()  asm volatile("cp.async.wait_group 0;" ::: "memory")

// stage v1 K16-chunk c into buffer (c & 3)
__device__ __forceinline__ void stage_v1_chunk(uint32_t sBu, const char* v1src, int tid, int c) {
    const int buf = c & 3;
#pragma unroll
    for (int q = 0; q < 2; ++q) {
        int idx = tid + q * 512;
        if (idx < 768) {
            int n = idx >> 1, h = idx & 1;
            cp16(sBu + buf * BUF_B + n * 48 + h * 16,
                 v1src + (size_t)n * 768 + c * 32 + h * 16);
        }
    }
}
// stage V 16-row chunk c into buffer (c & 3)
__device__ __forceinline__ void stage_v_chunk(uint32_t sBu, const char* vsrc, int tid, int c) {
    const int buf = c & 3;
#pragma unroll
    for (int q = 0; q < 2; ++q) {
        int idx = tid + q * 512;
        if (idx < 768) {
            int row = idx / 48, col = idx % 48;
            cp16(sBu + buf * BUF_B + row * 784 + col * 16,
                 vsrc + (size_t)c * 12288 + (size_t)idx * 16);
        }
    }
}

// ---------------------------------------------------------------------------
// prep kernel, grid (6, 386): by<2 -> linear slab; by>=2 -> x2 bf16 + colsum
// ---------------------------------------------------------------------------
constexpr int SMEM_PREP = (32 * 17 + 384 * 17) * 4;   // 28288

__global__ __launch_bounds__(256) void prep_kernel(const float* __restrict__ x1,
                                                   const float* __restrict__ W,
                                                   const float* __restrict__ b,
                                                   const float* __restrict__ x2) {
    extern __shared__ float dsf[];
    const int tid = threadIdx.x;
    const int bx = blockIdx.x, by = blockIdx.y;

    if (by < 2) {
        // ------------- linear: v1[n][k] = sum_m x1[n][m]*W[k][m] + b[k] -------------
        float* sX = dsf;                // [32][17]
        float* sW = dsf + 32 * 17;      // [384][17]
        const int L = by * 6 + bx;
        const int n0 = L * 32;
        const int nl = (tid & 15) * 2;
        const int k0 = (tid >> 4) * 24;
        float acc[2][24];
#pragma unroll
        for (int r = 0; r < 2; ++r)
#pragma unroll
            for (int j = 0; j < 24; ++j) acc[r][j] = 0.0f;

        for (int m0 = 0; m0 < N; m0 += 16) {
#pragma unroll
            for (int q = 0; q < 2; ++q) {
                int idx = tid + q * 256;
                int n = idx >> 4, m = idx & 15;
                sX[n * 17 + m] = x1[(size_t)(n0 + n) * N + m0 + m];
            }
#pragma unroll
            for (int q = 0; q < 24; ++q) {
                int idx = tid + q * 256;
                int k = idx >> 4, m = idx & 15;
                sW[k * 17 + m] = W[(size_t)k * N + m0 + m];
            }
            __syncthreads();
#pragma unroll
            for (int mm = 0; mm < 16; ++mm) {
                float x0 = sX[nl * 17 + mm];
                float x1v = sX[(nl + 1) * 17 + mm];
#pragma unroll
                for (int j = 0; j < 24; ++j) {
                    float w = sW[(k0 + j) * 17 + mm];
                    acc[0][j] += x0 * w;
                    acc[1][j] += x1v * w;
                }
            }
            __syncthreads();
        }
#pragma unroll
        for (int r = 0; r < 2; ++r) {
            int n = n0 + nl + r;
            uint32_t* dst = reinterpret_cast<uint32_t*>(g_v1b + (size_t)n * N + k0);
#pragma unroll
            for (int j = 0; j < 12; ++j)
                dst[j] = bf2_pack(acc[r][2 * j] + __ldg(b + k0 + 2 * j),
                                  acc[r][2 * j + 1] + __ldg(b + k0 + 2 * j + 1));
        }
        return;
    }

    // ------------- x2 -> bf16 (direct) + colsum in registers -------------
    const int i = by - 2, s = bx;
    float4* red = reinterpret_cast<float4*>(dsf);   // [192] float4
    if (tid < 192) {
        const int c4 = tid % 96;       // float4 column group
        const int rh = tid / 96;       // row parity
        const float* src = x2 + ((size_t)i * N + s * 64) * N;
        __nv_bfloat16* dst = g_x2b + ((size_t)i * N + s * 64) * N;
        float4 sum = make_float4(0.f, 0.f, 0.f, 0.f);
#pragma unroll
        for (int q = 0; q < 32; ++q) {
            int r = rh + 2 * q;
            float4 f = __ldg(reinterpret_cast<const float4*>(src + (size_t)r * N) + c4);
            sum.x += f.x; sum.y += f.y; sum.z += f.z; sum.w += f.w;
            uint2 u = make_uint2(bf2_pack(f.x, f.y), bf2_pack(f.z, f.w));
            *reinterpret_cast<uint2*>(dst + (size_t)r * N + c4 * 4) = u;
        }
        red[tid] = sum;
    }
    __syncthreads();
    if (tid < 96) {
        float4 a = red[tid], c = red[tid + 96];
        a.x += c.x; a.y += c.y; a.z += c.z; a.w += c.w;
        *reinterpret_cast<float4*>(g_cs6 + ((size_t)i * 6 + s) * N + tid * 4) = a;
    }
}

// ---------------------------------------------------------------------------
// Fused attention: 512 threads, 16 warps = 4 row-groups x 4 col-groups.
// 2 chunks per barrier cycle, 4 staging buffers.
// ---------------------------------------------------------------------------
__global__ __launch_bounds__(512, 1)
void attn_kernel(float* __restrict__ out) {
    extern __shared__ char smem[];
    __nv_bfloat16* sQ = reinterpret_cast<__nv_bfloat16*>(smem);
    float* srow = reinterpret_cast<float*>(smem + OFF_SROW);   // [4 wc][128 rows]
    float* cs_s = reinterpret_cast<float*>(smem + OFF_CS);

    const int tid = threadIdx.x;
    const int lane = tid & 31;
    const int warp = tid >> 5;
    const int wr = warp & 3;       // rows wr*32..+32
    const int wc = warp >> 2;      // cols wc*96..+96
    const int i = blockIdx.y;
    const int j0 = blockIdx.x * 128;

    const uint32_t sQu = smem_u32(smem);
    const uint32_t sBu = sQu + OFF_BUF;

    const int rowA = (lane & 7) + ((lane >> 3) & 1) * 8;
    const int colA = (lane >> 4) * 8;
    const uint32_t aBase = sQu + ((wr * 32 + rowA) * QS + colA) * 2;

    const int rowB = (lane & 7) + ((lane >> 4) & 1) * 8;
    const int colB = ((lane >> 3) & 1) * 8;
    const uint32_t bBase1 = sBu + (rowB * BS + colB) * 2;

    const int rowV = (lane & 7) + ((lane >> 3) & 1) * 8;
    const int colV = ((lane >> 4) & 1) * 8;
    const uint32_t bBase2 = sBu + (rowV * VS + colV) * 2;

    // ---- stage Q (contiguous 96KB bf16) + v1 chunks 0,1 (one commit group) ----
    const char* qsrc = reinterpret_cast<const char*>(g_x2b + ((size_t)i * N + j0) * N);
#pragma unroll
    for (int q = 0; q < 12; ++q) {
        int idx = tid + q * 512;           // 6144 transfers of 16B
        int row = idx / 48, c = idx % 48;
        cp16(sQu + row * 784 + c * 16, qsrc + (size_t)idx * 16);
    }
    const char* v1src = reinterpret_cast<const char*>(g_v1b);
    stage_v1_chunk(sBu, v1src, tid, 0);
    stage_v1_chunk(sBu, v1src, tid, 1);
    CP_COMMIT();

    float acc[2][12][4];
#pragma unroll
    for (int ma = 0; ma < 2; ++ma)
#pragma unroll
        for (int na = 0; na < 12; ++na)
#pragma unroll
            for (int r = 0; r < 4; ++r) acc[ma][na][r] = 0.0f;

    // =================== GEMM1: S = Q @ v1^T (12 pair-iterations) ===================
    for (int jj = 0; jj < 12; ++jj) {
        CP_WAIT0();
        __syncthreads();
        if (jj < 11) {
            stage_v1_chunk(sBu, v1src, tid, 2 * jj + 2);
            stage_v1_chunk(sBu, v1src, tid, 2 * jj + 3);
            CP_COMMIT();
        }
#pragma unroll
        for (int cc = 0; cc < 2; ++cc) {
            const int kc = 2 * jj + cc;
            const int buf = kc & 3;
            uint32_t a[2][4];
#pragma unroll
            for (int ma = 0; ma < 2; ++ma)
                ldm4(a[ma], aBase + (ma * 16 * QS + kc * 16) * 2);
#pragma unroll
            for (int nbx = 0; nbx < 6; ++nbx) {
                uint32_t bfr[4];
                ldm4(bfr, bBase1 + buf * BUF_B + (wc * 96 + nbx * 16) * 48);
#pragma unroll
                for (int ma = 0; ma < 2; ++ma) {
                    mma16816(acc[ma][2 * nbx], a[ma], bfr[0], bfr[1]);
                    mma16816(acc[ma][2 * nbx + 1], a[ma], bfr[2], bfr[3]);
                }
            }
        }
    }

    // ---- prefetch V chunks 0,1 (bufs 0,1 free since pair-iter 10; overlap softmax) ----
    const char* vsrc = reinterpret_cast<const char*>(g_x2b + (size_t)i * N * N);
    stage_v_chunk(sBu, vsrc, tid, 0);
    stage_v_chunk(sBu, vsrc, tid, 1);
    CP_COMMIT();

    // ---- colsum -> smem ----
    if (tid < 384) {
        float s0 = 0.f;
#pragma unroll
        for (int p = 0; p < 6; ++p) s0 += __ldg(g_cs6 + ((size_t)i * 6 + p) * N + tid);
        cs_s[tid] = s0;
    }

    // =================== softmax: delta = e/s - 1/N (bf16 into sQ) ===================
    float rs[2][2] = {{0.f, 0.f}, {0.f, 0.f}};
#pragma unroll
    for (int ma = 0; ma < 2; ++ma)
#pragma unroll
        for (int na = 0; na < 12; ++na) {
            float* d = acc[ma][na];
            d[0] = __expf(d[0] * SCALE_INV);
            d[1] = __expf(d[1] * SCALE_INV);
            d[2] = __expf(d[2] * SCALE_INV);
            d[3] = __expf(d[3] * SCALE_INV);
            rs[ma][0] += d[0] + d[1];
            rs[ma][1] += d[2] + d[3];
        }
#pragma unroll
    for (int ma = 0; ma < 2; ++ma)
#pragma unroll
        for (int h = 0; h < 2; ++h) {
            rs[ma][h] += __shfl_xor_sync(0xffffffffu, rs[ma][h], 1);
            rs[ma][h] += __shfl_xor_sync(0xffffffffu, rs[ma][h], 2);
        }
    if ((lane & 3) == 0) {
#pragma unroll
        for (int ma = 0; ma < 2; ++ma)
#pragma unroll
            for (int h = 0; h < 2; ++h)
                srow[wc * 128 + wr * 32 + ma * 16 + h * 8 + (lane >> 2)] = rs[ma][h];
    }
    __syncthreads();
    float invs[2][2];
#pragma unroll
    for (int ma = 0; ma < 2; ++ma)
#pragma unroll
        for (int h = 0; h < 2; ++h) {
            int r = wr * 32 + ma * 16 + h * 8 + (lane >> 2);
            invs[ma][h] = 1.0f / (srow[r] + srow[128 + r] + srow[256 + r] + srow[384 + r]);
        }
#pragma unroll
    for (int ma = 0; ma < 2; ++ma)
#pragma unroll
        for (int na = 0; na < 12; ++na) {
            int r = wr * 32 + ma * 16 + (lane >> 2);
            int c = wc * 96 + (na >> 1) * 16 + (na & 1) * 8 + (lane & 3) * 2;
            float* d = acc[ma][na];
            *reinterpret_cast<uint32_t*>(sQ + r * QS + c) =
                bf2_pack(d[0] * invs[ma][0] - INV_N, d[1] * invs[ma][0] - INV_N);
            *reinterpret_cast<uint32_t*>(sQ + (r + 8) * QS + c) =
                bf2_pack(d[2] * invs[ma][1] - INV_N, d[3] * invs[ma][1] - INV_N);
        }
    __syncthreads();

    // =================== GEMM2: corr = delta @ V (12 pair-iterations) ===================
#pragma unroll
    for (int ma = 0; ma < 2; ++ma)
#pragma unroll
        for (int na = 0; na < 12; ++na)
#pragma unroll
            for (int r = 0; r < 4; ++r) acc[ma][na][r] = 0.0f;

    for (int jj = 0; jj < 12; ++jj) {
        CP_WAIT0();
        __syncthreads();
        if (jj < 11) {
            stage_v_chunk(sBu, vsrc, tid, 2 * jj + 2);
            stage_v_chunk(sBu, vsrc, tid, 2 * jj + 3);
            CP_COMMIT();
        }
#pragma unroll
        for (int cc = 0; cc < 2; ++cc) {
            const int nc = 2 * jj + cc;
            const int buf = nc & 3;
            uint32_t a[2][4];
#pragma unroll
            for (int ma = 0; ma < 2; ++ma)
                ldm4(a[ma], aBase + (ma * 16 * QS + nc * 16) * 2);
#pragma unroll
            for (int nbx = 0; nbx < 6; ++nbx) {
                uint32_t bfr[4];
                ldm4t(bfr, bBase2 + buf * BUF_B + (wc * 96 + nbx * 16) * 2);
#pragma unroll
                for (int ma = 0; ma < 2; ++ma) {
                    mma16816(acc[ma][2 * nbx], a[ma], bfr[0], bfr[1]);
                    mma16816(acc[ma][2 * nbx + 1], a[ma], bfr[2], bfr[3]);
                }
            }
        }
    }

    // =================== epilogue: out = corr + colsum/384 ===================
#pragma unroll
    for (int ma = 0; ma < 2; ++ma)
#pragma unroll
        for (int nbx = 0; nbx < 6; ++nbx)
#pragma unroll
            for (int ct = 0; ct < 2; ++ct) {
                int na = nbx * 2 + ct;
                int r = j0 + wr * 32 + ma * 16 + (lane >> 2);
                int c = wc * 96 + nbx * 16 + ct * 8 + (lane & 3) * 2;
                float cs0 = cs_s[c] * INV_N;
                float cs1 = cs_s[c + 1] * INV_N;
                float* d = acc[ma][na];
                float2 o0 = make_float2(d[0] + cs0, d[1] + cs1);
                float2 o1 = make_float2(d[2] + cs0, d[3] + cs1);
                *reinterpret_cast<float2*>(out + ((size_t)i * N + r) * N + c) = o0;
                *reinterpret_cast<float2*>(out + ((size_t)i * N + r + 8) * N + c) = o1;
            }
}

// ---------------------------------------------------------------------------
extern "C" void kernel_launch(void* const* d_in, const int* in_sizes, int n_in,
                              void* d_out, int out_size) {
    const float* x1 = (const float*)d_in[0];
    const float* x2 = (const float*)d_in[1];
    const float* W  = (const float*)d_in[2];
    const float* b  = (const float*)d_in[3];
    float* out = (float*)d_out;
    (void)in_sizes; (void)n_in; (void)out_size;

    {
        cudaFuncSetAttribute(prep_kernel, cudaFuncAttributeMaxDynamicSharedMemorySize, SMEM_PREP);
        dim3 g(6, 386);
        prep_kernel<<<g, 256, SMEM_PREP>>>(x1, W, b, x2);
    }
    {
        cudaFuncSetAttribute(attn_kernel, cudaFuncAttributeMaxDynamicSharedMemorySize, SMEM_ATTN);
        dim3 g(3, 384);
        attn_kernel<<<g, 512, SMEM_ATTN>>>(out);
    }
}

// round 14
// speedup vs baseline: 2.1038x; 1.0959x over previous
#include <cuda_runtime.h>
#include <cuda_bf16.h>
#include <cstdint>

// out[i] = softmax((x2[i] @ v1^T)/1000) @ x2[i],  v1 = x1@W.T + b,  N=384.
// P = 1/384 + delta  ->  out = colsum(x2[i])/384 + delta @ x2[i].
// GEMMs: mma.sync m16n8k16 bf16 (R11 geometry, proven).
// R14: staging via cp.async.bulk (one DMA op per chunk, mbarrier complete_tx)
//      from gmem images prebaked in the exact padded smem layouts.

constexpr int N = 384;
constexpr float SCALE_INV = 1.0f / 1000.0f;
constexpr float INV_N = 1.0f / 384.0f;

constexpr int QS = 392;   // sQ row stride (halves): 384 + 8 pad (= g_xp row stride)
constexpr int BS = 24;    // GEMM1 B row stride (halves): 16 + 8 pad (= g_v1p row stride)
constexpr int VS = 392;   // GEMM2 B row stride (halves) (= g_xp row stride)

constexpr int SQ_BYTES = 128 * QS * 2;        // 100352
constexpr int BUF_B    = 18432;               // v1 chunk: 384*48B; V chunk: 16*784=12544 fits
constexpr int OFF_BUF  = SQ_BYTES;
constexpr int OFF_SROW = OFF_BUF + 3 * BUF_B;            // 155648
constexpr int OFF_CS   = OFF_SROW + 512 * 4;             // 157696
constexpr int SMEM_ATTN = OFF_CS + 384 * 4;              // 159232

// padded gmem images (zero-initialized __device__ globals)
__device__ __align__(1024) __nv_bfloat16 g_xp[(size_t)N * N * QS];   // x2 bf16, 784B rows
__device__ __align__(1024) __nv_bfloat16 g_v1p[24 * N * BS];         // v1 K16-chunks, 48B rows
__device__ float g_cs6[(size_t)N * 6 * N];                           // partial colsums

// ---------------------------------------------------------------------------
__device__ __forceinline__ uint32_t smem_u32(const void* p) {
    uint32_t a;
    asm("{ .reg .u64 t; cvta.to.shared.u64 t, %1; cvt.u32.u64 %0, t; }" : "=r"(a) : "l"(p));
    return a;
}
__device__ __forceinline__ void ldm4(uint32_t* r, uint32_t addr) {
    asm volatile("ldmatrix.sync.aligned.m8n8.x4.shared.b16 {%0,%1,%2,%3},[%4];"
                 : "=r"(r[0]), "=r"(r[1]), "=r"(r[2]), "=r"(r[3]) : "r"(addr));
}
__device__ __forceinline__ void ldm4t(uint32_t* r, uint32_t addr) {
    asm volatile("ldmatrix.sync.aligned.m8n8.x4.trans.shared.b16 {%0,%1,%2,%3},[%4];"
                 : "=r"(r[0]), "=r"(r[1]), "=r"(r[2]), "=r"(r[3]) : "r"(addr));
}
__device__ __forceinline__ void mma16816(float* d, const uint32_t* a, uint32_t b0, uint32_t b1) {
    asm volatile("mma.sync.aligned.m16n8k16.row.col.f32.bf16.bf16.f32 "
                 "{%0,%1,%2,%3},{%4,%5,%6,%7},{%8,%9},{%0,%1,%2,%3};"
                 : "+f"(d[0]), "+f"(d[1]), "+f"(d[2]), "+f"(d[3])
                 : "r"(a[0]), "r"(a[1]), "r"(a[2]), "r"(a[3]), "r"(b0), "r"(b1));
}
__device__ __forceinline__ uint32_t bf2_pack(float a, float b) {
    __nv_bfloat162 h = __floats2bfloat162_rn(a, b);
    return *reinterpret_cast<uint32_t*>(&h);
}
// ---- bulk copy + mbarrier ----
__device__ __forceinline__ void bulk_cp(uint32_t dst, const void* src, uint32_t bytes,
                                        uint32_t mbar) {
    asm volatile("cp.async.bulk.shared::cluster.global.mbarrier::complete_tx::bytes "
                 "[%0], [%1], %2, [%3];"
                 :: "r"(dst), "l"(src), "r"(bytes), "r"(mbar) : "memory");
}
__device__ __forceinline__ void mbar_init(uint32_t mb, uint32_t cnt) {
    asm volatile("mbarrier.init.shared.b64 [%0], %1;" :: "r"(mb), "r"(cnt) : "memory");
}
__device__ __forceinline__ void mbar_expect_tx(uint32_t mb, uint32_t bytes) {
    asm volatile("mbarrier.arrive.expect_tx.shared.b64 _, [%0], %1;"
                 :: "r"(mb), "r"(bytes) : "memory");
}
__device__ __forceinline__ void mbar_wait(uint32_t mb, uint32_t parity) {
    asm volatile(
        "{\n .reg .pred P;\n"
        "W_%=:\n mbarrier.try_wait.parity.shared.b64 P, [%0], %1;\n"
        " @P bra.uni D_%=;\n bra.uni W_%=;\nD_%=:\n}"
        :: "r"(mb), "r"(parity) : "memory");
}

// ---------------------------------------------------------------------------
// prep kernel, grid (6, 386): by<2 -> linear slab; by>=2 -> x2 padded image + colsum
// ---------------------------------------------------------------------------
constexpr int SMEM_PREP = (32 * 17 + 384 * 17) * 4;   // 28288

__global__ __launch_bounds__(256) void prep_kernel(const float* __restrict__ x1,
                                                   const float* __restrict__ W,
                                                   const float* __restrict__ b,
                                                   const float* __restrict__ x2) {
    extern __shared__ float dsf[];
    const int tid = threadIdx.x;
    const int bx = blockIdx.x, by = blockIdx.y;

    if (by < 2) {
        // ------------- linear: v1[n][k] = sum_m x1[n][m]*W[k][m] + b[k] -------------
        float* sX = dsf;                // [32][17]
        float* sW = dsf + 32 * 17;      // [384][17]
        const int L = by * 6 + bx;
        const int n0 = L * 32;
        const int nl = (tid & 15) * 2;
        const int k0 = (tid >> 4) * 24;
        float acc[2][24];
#pragma unroll
        for (int r = 0; r < 2; ++r)
#pragma unroll
            for (int j = 0; j < 24; ++j) acc[r][j] = 0.0f;

        for (int m0 = 0; m0 < N; m0 += 16) {
#pragma unroll
            for (int q = 0; q < 2; ++q) {
                int idx = tid + q * 256;
                int n = idx >> 4, m = idx & 15;
                sX[n * 17 + m] = x1[(size_t)(n0 + n) * N + m0 + m];
            }
#pragma unroll
            for (int q = 0; q < 24; ++q) {
                int idx = tid + q * 256;
                int k = idx >> 4, m = idx & 15;
                sW[k * 17 + m] = W[(size_t)k * N + m0 + m];
            }
            __syncthreads();
#pragma unroll
            for (int mm = 0; mm < 16; ++mm) {
                float x0 = sX[nl * 17 + mm];
                float x1v = sX[(nl + 1) * 17 + mm];
#pragma unroll
                for (int j = 0; j < 24; ++j) {
                    float w = sW[(k0 + j) * 17 + mm];
                    acc[0][j] += x0 * w;
                    acc[1][j] += x1v * w;
                }
            }
            __syncthreads();
        }
        // scatter into chunk-major padded layout g_v1p[kc][n][kk]
#pragma unroll
        for (int r = 0; r < 2; ++r) {
            int n = n0 + nl + r;
#pragma unroll
            for (int j = 0; j < 24; ++j) {
                int k = k0 + j;
                g_v1p[((size_t)(k >> 4) * N + n) * BS + (k & 15)] =
                    __float2bfloat16(acc[r][j] + __ldg(b + k));
            }
        }
        return;
    }

    // ------------- x2 -> padded bf16 image + colsum in registers -------------
    const int i = by - 2, s = bx;
    float4* red = reinterpret_cast<float4*>(dsf);   // [192] float4
    if (tid < 192) {
        const int c4 = tid % 96;       // float4 column group
        const int rh = tid / 96;       // row parity
        const float* src = x2 + ((size_t)i * N + s * 64) * N;
        __nv_bfloat16* dst = g_xp + ((size_t)i * N + s * 64) * QS;
        float4 sum = make_float4(0.f, 0.f, 0.f, 0.f);
#pragma unroll
        for (int q = 0; q < 32; ++q) {
            int r = rh + 2 * q;
            float4 f = __ldg(reinterpret_cast<const float4*>(src + (size_t)r * N) + c4);
            sum.x += f.x; sum.y += f.y; sum.z += f.z; sum.w += f.w;
            uint2 u = make_uint2(bf2_pack(f.x, f.y), bf2_pack(f.z, f.w));
            *reinterpret_cast<uint2*>(dst + (size_t)r * QS + c4 * 4) = u;
        }
        red[tid] = sum;
    }
    __syncthreads();
    if (tid < 96) {
        float4 a = red[tid], c = red[tid + 96];
        a.x += c.x; a.y += c.y; a.z += c.z; a.w += c.w;
        *reinterpret_cast<float4*>(g_cs6 + ((size_t)i * 6 + s) * N + tid * 4) = a;
    }
}

// ---------------------------------------------------------------------------
// Fused attention: 512 threads, 16 warps = 4 row x 4 col groups (R11 geometry).
// Staging: cp.async.bulk per chunk, 3 buffers, mbarrier parity = (chunk/3)&1.
// ---------------------------------------------------------------------------
__global__ __launch_bounds__(512, 1)
void attn_kernel(float* __restrict__ out) {
    extern __shared__ char smem[];
    __shared__ __align__(8) uint64_t s_mbar[4];   // [0..2]=buffers, [3]=Q
    __nv_bfloat16* sQ = reinterpret_cast<__nv_bfloat16*>(smem);
    float* srow = reinterpret_cast<float*>(smem + OFF_SROW);
    float* cs_s = reinterpret_cast<float*>(smem + OFF_CS);

    const int tid = threadIdx.x;
    const int lane = tid & 31;
    const int warp = tid >> 5;
    const int wr = warp & 3;       // rows wr*32..+32
    const int wc = warp >> 2;      // cols wc*96..+96
    const int i = blockIdx.y;
    const int j0 = blockIdx.x * 128;

    const uint32_t sQu = smem_u32(smem);
    const uint32_t sBu = sQu + OFF_BUF;
    uint32_t mb[4];
#pragma unroll
    for (int q = 0; q < 4; ++q) mb[q] = smem_u32(&s_mbar[q]);

    const int rowA = (lane & 7) + ((lane >> 3) & 1) * 8;
    const int colA = (lane >> 4) * 8;
    const uint32_t aBase = sQu + ((wr * 32 + rowA) * QS + colA) * 2;

    const int rowB = (lane & 7) + ((lane >> 4) & 1) * 8;
    const int colB = ((lane >> 3) & 1) * 8;
    const uint32_t bBase1 = sBu + (rowB * BS + colB) * 2;

    const int rowV = (lane & 7) + ((lane >> 3) & 1) * 8;
    const int colV = ((lane >> 4) & 1) * 8;
    const uint32_t bBase2 = sBu + (rowV * VS + colV) * 2;

    // ---- init mbarriers, then kick off Q + v1 chunks 0,1 ----
    if (tid == 0) {
#pragma unroll
        for (int q = 0; q < 4; ++q) mbar_init(mb[q], 1);
    }
    __syncthreads();

    const char* qsrc = reinterpret_cast<const char*>(g_xp + ((size_t)i * N + j0) * QS);
    const char* v1src = reinterpret_cast<const char*>(g_v1p);
    const char* vsrc = reinterpret_cast<const char*>(g_xp + (size_t)i * N * QS);
    if (tid == 0) {
        mbar_expect_tx(mb[3], SQ_BYTES);
        bulk_cp(sQu, qsrc, SQ_BYTES, mb[3]);
        mbar_expect_tx(mb[0], BUF_B);
        bulk_cp(sBu, v1src, BUF_B, mb[0]);
        mbar_expect_tx(mb[1], BUF_B);
        bulk_cp(sBu + BUF_B, v1src + BUF_B, BUF_B, mb[1]);
    }

    float acc[2][12][4];
#pragma unroll
    for (int ma = 0; ma < 2; ++ma)
#pragma unroll
        for (int na = 0; na < 12; ++na)
#pragma unroll
            for (int r = 0; r < 4; ++r) acc[ma][na][r] = 0.0f;

    mbar_wait(mb[3], 0);   // Q ready

    // =================== GEMM1: S = Q @ v1^T ===================
    for (int kc = 0; kc < 24; ++kc) {
        const int buf = kc % 3;
        mbar_wait(mb[buf], (kc / 3) & 1);
        __syncthreads();
        if (kc + 2 < 24 && tid == 0) {
            const int nb = (kc + 2) % 3;
            mbar_expect_tx(mb[nb], BUF_B);
            bulk_cp(sBu + nb * BUF_B, v1src + (size_t)(kc + 2) * BUF_B, BUF_B, mb[nb]);
        }
        uint32_t a[2][4];
#pragma unroll
        for (int ma = 0; ma < 2; ++ma)
            ldm4(a[ma], aBase + (ma * 16 * QS + kc * 16) * 2);
#pragma unroll
        for (int nbx = 0; nbx < 6; ++nbx) {
            uint32_t bfr[4];
            ldm4(bfr, bBase1 + buf * BUF_B + (wc * 96 + nbx * 16) * 48);
#pragma unroll
            for (int ma = 0; ma < 2; ++ma) {
                mma16816(acc[ma][2 * nbx], a[ma], bfr[0], bfr[1]);
                mma16816(acc[ma][2 * nbx + 1], a[ma], bfr[2], bfr[3]);
            }
        }
    }

    // ---- kick off V chunks 0,1 (bufs 0,1 free; overlaps softmax) ----
    if (tid == 0) {
        mbar_expect_tx(mb[0], 16 * VS * 2);
        bulk_cp(sBu, vsrc, 16 * VS * 2, mb[0]);
        mbar_expect_tx(mb[1], 16 * VS * 2);
        bulk_cp(sBu + BUF_B, vsrc + (size_t)16 * VS * 2, 16 * VS * 2, mb[1]);
    }

    // ---- colsum -> smem ----
    if (tid < 384) {
        float s0 = 0.f;
#pragma unroll
        for (int p = 0; p < 6; ++p) s0 += __ldg(g_cs6 + ((size_t)i * 6 + p) * N + tid);
        cs_s[tid] = s0;
    }

    // =================== softmax: delta = e/s - 1/N (bf16 into sQ) ===================
    float rs[2][2] = {{0.f, 0.f}, {0.f, 0.f}};
#pragma unroll
    for (int ma = 0; ma < 2; ++ma)
#pragma unroll
        for (int na = 0; na < 12; ++na) {
            float* d = acc[ma][na];
            d[0] = __expf(d[0] * SCALE_INV);
            d[1] = __expf(d[1] * SCALE_INV);
            d[2] = __expf(d[2] * SCALE_INV);
            d[3] = __expf(d[3] * SCALE_INV);
            rs[ma][0] += d[0] + d[1];
            rs[ma][1] += d[2] + d[3];
        }
#pragma unroll
    for (int ma = 0; ma < 2; ++ma)
#pragma unroll
        for (int h = 0; h < 2; ++h) {
            rs[ma][h] += __shfl_xor_sync(0xffffffffu, rs[ma][h], 1);
            rs[ma][h] += __shfl_xor_sync(0xffffffffu, rs[ma][h], 2);
        }
    if ((lane & 3) == 0) {
#pragma unroll
        for (int ma = 0; ma < 2; ++ma)
#pragma unroll
            for (int h = 0; h < 2; ++h)
                srow[wc * 128 + wr * 32 + ma * 16 + h * 8 + (lane >> 2)] = rs[ma][h];
    }
    __syncthreads();
    float invs[2][2];
#pragma unroll
    for (int ma = 0; ma < 2; ++ma)
#pragma unroll
        for (int h = 0; h < 2; ++h) {
            int r = wr * 32 + ma * 16 + h * 8 + (lane >> 2);
            invs[ma][h] = 1.0f / (srow[r] + srow[128 + r] + srow[256 + r] + srow[384 + r]);
        }
#pragma unroll
    for (int ma = 0; ma < 2; ++ma)
#pragma unroll
        for (int na = 0; na < 12; ++na) {
            int r = wr * 32 + ma * 16 + (lane >> 2);
            int c = wc * 96 + (na >> 1) * 16 + (na & 1) * 8 + (lane & 3) * 2;
            float* d = acc[ma][na];
            *reinterpret_cast<uint32_t*>(sQ + r * QS + c) =
                bf2_pack(d[0] * invs[ma][0] - INV_N, d[1] * invs[ma][0] - INV_N);
            *reinterpret_cast<uint32_t*>(sQ + (r + 8) * QS + c) =
                bf2_pack(d[2] * invs[ma][1] - INV_N, d[3] * invs[ma][1] - INV_N);
        }
    __syncthreads();

    // =================== GEMM2: corr = delta @ V ===================
#pragma unroll
    for (int ma = 0; ma < 2; ++ma)
#pragma unroll
        for (int na = 0; na < 12; ++na)
#pragma unroll
            for (int r = 0; r < 4; ++r) acc[ma][na][r] = 0.0f;

    for (int nc = 0; nc < 24; ++nc) {
        const int buf = nc % 3;
        mbar_wait(mb[buf], (nc / 3) & 1);
        __syncthreads();
        if (nc + 2 < 24 && tid == 0) {
            const int nb = (nc + 2) % 3;
            mbar_expect_tx(mb[nb], 16 * VS * 2);
            bulk_cp(sBu + nb * BUF_B, vsrc + (size_t)(nc + 2) * 16 * VS * 2,
                    16 * VS * 2, mb[nb]);
        }
        uint32_t a[2][4];
#pragma unroll
        for (int ma = 0; ma < 2; ++ma)
            ldm4(a[ma], aBase + (ma * 16 * QS + nc * 16) * 2);
#pragma unroll
        for (int nbx = 0; nbx < 6; ++nbx) {
            uint32_t bfr[4];
            ldm4t(bfr, bBase2 + buf * BUF_B + (wc * 96 + nbx * 16) * 2);
#pragma unroll
            for (int ma = 0; ma < 2; ++ma) {
                mma16816(acc[ma][2 * nbx], a[ma], bfr[0], bfr[1]);
                mma16816(acc[ma][2 * nbx + 1], a[ma], bfr[2], bfr[3]);
            }
        }
    }

    // =================== epilogue: out = corr + colsum/384 ===================
#pragma unroll
    for (int ma = 0; ma < 2; ++ma)
#pragma unroll
        for (int nbx = 0; nbx < 6; ++nbx)
#pragma unroll
            for (int ct = 0; ct < 2; ++ct) {
                int na = nbx * 2 + ct;
                int r = j0 + wr * 32 + ma * 16 + (lane >> 2);
                int c = wc * 96 + nbx * 16 + ct * 8 + (lane & 3) * 2;
                float cs0 = cs_s[c] * INV_N;
                float cs1 = cs_s[c + 1] * INV_N;
                float* d = acc[ma][na];
                float2 o0 = make_float2(d[0] + cs0, d[1] + cs1);
                float2 o1 = make_float2(d[2] + cs0, d[3] + cs1);
                *reinterpret_cast<float2*>(out + ((size_t)i * N + r) * N + c) = o0;
                *reinterpret_cast<float2*>(out + ((size_t)i * N + r + 8) * N + c) = o1;
            }
}

// ---------------------------------------------------------------------------
extern "C" void kernel_launch(void* const* d_in, const int* in_sizes, int n_in,
                              void* d_out, int out_size) {
    const float* x1 = (const float*)d_in[0];
    const float* x2 = (const float*)d_in[1];
    const float* W  = (const float*)d_in[2];
    const float* b  = (const float*)d_in[3];
    float* out = (float*)d_out;
    (void)in_sizes; (void)n_in; (void)out_size;

    {
        cudaFuncSetAttribute(prep_kernel, cudaFuncAttributeMaxDynamicSharedMemorySize, SMEM_PREP);
        dim3 g(6, 386);
        prep_kernel<<<g, 256, SMEM_PREP>>>(x1, W, b, x2);
    }
    {
        cudaFuncSetAttribute(attn_kernel, cudaFuncAttributeMaxDynamicSharedMemorySize, SMEM_ATTN);
        dim3 g(3, 384);
        attn_kernel<<<g, 512, SMEM_ATTN>>>(out);
    }
}

// round 15
// speedup vs baseline: 2.1258x; 1.0104x over previous
#include <cuda_runtime.h>
#include <cuda_bf16.h>
#include <cstdint>

// out[i] = softmax((x2[i] @ v1^T)/1000) @ x2[i],  v1 = x1@W.T + b,  N=384.
// P = 1/384 + delta  ->  out = colsum(x2[i])/384 + delta @ x2[i].
// GEMMs: mma.sync m16n8k16 bf16 (R11/R14 geometry, proven).
// R15 = R14 (bulk-DMA staging) + register double-buffered B fragments in the
//       inner loop so LDSM latency is covered by the HMMA stream.

constexpr int N = 384;
constexpr float SCALE_INV = 1.0f / 1000.0f;
constexpr float INV_N = 1.0f / 384.0f;

constexpr int QS = 392;   // sQ row stride (halves): 384 + 8 pad (= g_xp row stride)
constexpr int BS = 24;    // GEMM1 B row stride (halves): 16 + 8 pad (= g_v1p row stride)
constexpr int VS = 392;   // GEMM2 B row stride (halves) (= g_xp row stride)

constexpr int SQ_BYTES = 128 * QS * 2;        // 100352
constexpr int BUF_B    = 18432;               // v1 chunk: 384*48B; V chunk: 16*784=12544 fits
constexpr int OFF_BUF  = SQ_BYTES;
constexpr int OFF_SROW = OFF_BUF + 3 * BUF_B;            // 155648
constexpr int OFF_CS   = OFF_SROW + 512 * 4;             // 157696
constexpr int SMEM_ATTN = OFF_CS + 384 * 4;              // 159232

// padded gmem images (zero-initialized __device__ globals)
__device__ __align__(1024) __nv_bfloat16 g_xp[(size_t)N * N * QS];   // x2 bf16, 784B rows
__device__ __align__(1024) __nv_bfloat16 g_v1p[24 * N * BS];         // v1 K16-chunks, 48B rows
__device__ float g_cs6[(size_t)N * 6 * N];                           // partial colsums

// ---------------------------------------------------------------------------
__device__ __forceinline__ uint32_t smem_u32(const void* p) {
    uint32_t a;
    asm("{ .reg .u64 t; cvta.to.shared.u64 t, %1; cvt.u32.u64 %0, t; }" : "=r"(a) : "l"(p));
    return a;
}
__device__ __forceinline__ void ldm4(uint32_t* r, uint32_t addr) {
    asm volatile("ldmatrix.sync.aligned.m8n8.x4.shared.b16 {%0,%1,%2,%3},[%4];"
                 : "=r"(r[0]), "=r"(r[1]), "=r"(r[2]), "=r"(r[3]) : "r"(addr));
}
__device__ __forceinline__ void ldm4t(uint32_t* r, uint32_t addr) {
    asm volatile("ldmatrix.sync.aligned.m8n8.x4.trans.shared.b16 {%0,%1,%2,%3},[%4];"
                 : "=r"(r[0]), "=r"(r[1]), "=r"(r[2]), "=r"(r[3]) : "r"(addr));
}
__device__ __forceinline__ void mma16816(float* d, const uint32_t* a, uint32_t b0, uint32_t b1) {
    asm volatile("mma.sync.aligned.m16n8k16.row.col.f32.bf16.bf16.f32 "
                 "{%0,%1,%2,%3},{%4,%5,%6,%7},{%8,%9},{%0,%1,%2,%3};"
                 : "+f"(d[0]), "+f"(d[1]), "+f"(d[2]), "+f"(d[3])
                 : "r"(a[0]), "r"(a[1]), "r"(a[2]), "r"(a[3]), "r"(b0), "r"(b1));
}
__device__ __forceinline__ uint32_t bf2_pack(float a, float b) {
    __nv_bfloat162 h = __floats2bfloat162_rn(a, b);
    return *reinterpret_cast<uint32_t*>(&h);
}
// ---- bulk copy + mbarrier ----
__device__ __forceinline__ void bulk_cp(uint32_t dst, const void* src, uint32_t bytes,
                                        uint32_t mbar) {
    asm volatile("cp.async.bulk.shared::cluster.global.mbarrier::complete_tx::bytes "
                 "[%0], [%1], %2, [%3];"
                 :: "r"(dst), "l"(src), "r"(bytes), "r"(mbar) : "memory");
}
__device__ __forceinline__ void mbar_init(uint32_t mb, uint32_t cnt) {
    asm volatile("mbarrier.init.shared.b64 [%0], %1;" :: "r"(mb), "r"(cnt) : "memory");
}
__device__ __forceinline__ void mbar_expect_tx(uint32_t mb, uint32_t bytes) {
    asm volatile("mbarrier.arrive.expect_tx.shared.b64 _, [%0], %1;"
                 :: "r"(mb), "r"(bytes) : "memory");
}
__device__ __forceinline__ void mbar_wait(uint32_t mb, uint32_t parity) {
    asm volatile(
        "{\n .reg .pred P;\n"
        "W_%=:\n mbarrier.try_wait.parity.shared.b64 P, [%0], %1;\n"
        " @P bra.uni D_%=;\n bra.uni W_%=;\nD_%=:\n}"
        :: "r"(mb), "r"(parity) : "memory");
}

// ---------------------------------------------------------------------------
// prep kernel, grid (6, 386): by<2 -> linear slab; by>=2 -> x2 padded image + colsum
// ---------------------------------------------------------------------------
constexpr int SMEM_PREP = (32 * 17 + 384 * 17) * 4;   // 28288

__global__ __launch_bounds__(256) void prep_kernel(const float* __restrict__ x1,
                                                   const float* __restrict__ W,
                                                   const float* __restrict__ b,
                                                   const float* __restrict__ x2) {
    extern __shared__ float dsf[];
    const int tid = threadIdx.x;
    const int bx = blockIdx.x, by = blockIdx.y;

    if (by < 2) {
        // ------------- linear: v1[n][k] = sum_m x1[n][m]*W[k][m] + b[k] -------------
        float* sX = dsf;                // [32][17]
        float* sW = dsf + 32 * 17;      // [384][17]
        const int L = by * 6 + bx;
        const int n0 = L * 32;
        const int nl = (tid & 15) * 2;
        const int k0 = (tid >> 4) * 24;
        float acc[2][24];
#pragma unroll
        for (int r = 0; r < 2; ++r)
#pragma unroll
            for (int j = 0; j < 24; ++j) acc[r][j] = 0.0f;

        for (int m0 = 0; m0 < N; m0 += 16) {
#pragma unroll
            for (int q = 0; q < 2; ++q) {
                int idx = tid + q * 256;
                int n = idx >> 4, m = idx & 15;
                sX[n * 17 + m] = x1[(size_t)(n0 + n) * N + m0 + m];
            }
#pragma unroll
            for (int q = 0; q < 24; ++q) {
                int idx = tid + q * 256;
                int k = idx >> 4, m = idx & 15;
                sW[k * 17 + m] = W[(size_t)k * N + m0 + m];
            }
            __syncthreads();
#pragma unroll
            for (int mm = 0; mm < 16; ++mm) {
                float x0 = sX[nl * 17 + mm];
                float x1v = sX[(nl + 1) * 17 + mm];
#pragma unroll
                for (int j = 0; j < 24; ++j) {
                    float w = sW[(k0 + j) * 17 + mm];
                    acc[0][j] += x0 * w;
                    acc[1][j] += x1v * w;
                }
            }
            __syncthreads();
        }
        // scatter into chunk-major padded layout g_v1p[kc][n][kk]
#pragma unroll
        for (int r = 0; r < 2; ++r) {
            int n = n0 + nl + r;
#pragma unroll
            for (int j = 0; j < 24; ++j) {
                int k = k0 + j;
                g_v1p[((size_t)(k >> 4) * N + n) * BS + (k & 15)] =
                    __float2bfloat16(acc[r][j] + __ldg(b + k));
            }
        }
        return;
    }

    // ------------- x2 -> padded bf16 image + colsum in registers -------------
    const int i = by - 2, s = bx;
    float4* red = reinterpret_cast<float4*>(dsf);   // [192] float4
    if (tid < 192) {
        const int c4 = tid % 96;       // float4 column group
        const int rh = tid / 96;       // row parity
        const float* src = x2 + ((size_t)i * N + s * 64) * N;
        __nv_bfloat16* dst = g_xp + ((size_t)i * N + s * 64) * QS;
        float4 sum = make_float4(0.f, 0.f, 0.f, 0.f);
#pragma unroll
        for (int q = 0; q < 32; ++q) {
            int r = rh + 2 * q;
            float4 f = __ldg(reinterpret_cast<const float4*>(src + (size_t)r * N) + c4);
            sum.x += f.x; sum.y += f.y; sum.z += f.z; sum.w += f.w;
            uint2 u = make_uint2(bf2_pack(f.x, f.y), bf2_pack(f.z, f.w));
            *reinterpret_cast<uint2*>(dst + (size_t)r * QS + c4 * 4) = u;
        }
        red[tid] = sum;
    }
    __syncthreads();
    if (tid < 96) {
        float4 a = red[tid], c = red[tid + 96];
        a.x += c.x; a.y += c.y; a.z += c.z; a.w += c.w;
        *reinterpret_cast<float4*>(g_cs6 + ((size_t)i * 6 + s) * N + tid * 4) = a;
    }
}

// ---------------------------------------------------------------------------
// Fused attention: 512 threads, 16 warps = 4 row x 4 col groups.
// Staging: cp.async.bulk per chunk, 3 buffers. Inner loop: B double-buffered
// in registers so each LDSM is covered by 4 HMMA of independent work.
// ---------------------------------------------------------------------------
__global__ __launch_bounds__(512, 1)
void attn_kernel(float* __restrict__ out) {
    extern __shared__ char smem[];
    __shared__ __align__(8) uint64_t s_mbar[4];   // [0..2]=buffers, [3]=Q
    __nv_bfloat16* sQ = reinterpret_cast<__nv_bfloat16*>(smem);
    float* srow = reinterpret_cast<float*>(smem + OFF_SROW);
    float* cs_s = reinterpret_cast<float*>(smem + OFF_CS);

    const int tid = threadIdx.x;
    const int lane = tid & 31;
    const int warp = tid >> 5;
    const int wr = warp & 3;       // rows wr*32..+32
    const int wc = warp >> 2;      // cols wc*96..+96
    const int i = blockIdx.y;
    const int j0 = blockIdx.x * 128;

    const uint32_t sQu = smem_u32(smem);
    const uint32_t sBu = sQu + OFF_BUF;
    uint32_t mb[4];
#pragma unroll
    for (int q = 0; q < 4; ++q) mb[q] = smem_u32(&s_mbar[q]);

    const int rowA = (lane & 7) + ((lane >> 3) & 1) * 8;
    const int colA = (lane >> 4) * 8;
    const uint32_t aBase = sQu + ((wr * 32 + rowA) * QS + colA) * 2;

    const int rowB = (lane & 7) + ((lane >> 4) & 1) * 8;
    const int colB = ((lane >> 3) & 1) * 8;
    const uint32_t bBase1 = sBu + (rowB * BS + colB) * 2;

    const int rowV = (lane & 7) + ((lane >> 3) & 1) * 8;
    const int colV = ((lane >> 4) & 1) * 8;
    const uint32_t bBase2 = sBu + (rowV * VS + colV) * 2;

    // ---- init mbarriers, then kick off Q + v1 chunks 0,1 ----
    if (tid == 0) {
#pragma unroll
        for (int q = 0; q < 4; ++q) mbar_init(mb[q], 1);
    }
    __syncthreads();

    const char* qsrc = reinterpret_cast<const char*>(g_xp + ((size_t)i * N + j0) * QS);
    const char* v1src = reinterpret_cast<const char*>(g_v1p);
    const char* vsrc = reinterpret_cast<const char*>(g_xp + (size_t)i * N * QS);
    if (tid == 0) {
        mbar_expect_tx(mb[3], SQ_BYTES);
        bulk_cp(sQu, qsrc, SQ_BYTES, mb[3]);
        mbar_expect_tx(mb[0], BUF_B);
        bulk_cp(sBu, v1src, BUF_B, mb[0]);
        mbar_expect_tx(mb[1], BUF_B);
        bulk_cp(sBu + BUF_B, v1src + BUF_B, BUF_B, mb[1]);
    }

    float acc[2][12][4];
#pragma unroll
    for (int ma = 0; ma < 2; ++ma)
#pragma unroll
        for (int na = 0; na < 12; ++na)
#pragma unroll
            for (int r = 0; r < 4; ++r) acc[ma][na][r] = 0.0f;

    mbar_wait(mb[3], 0);   // Q ready

    // =================== GEMM1: S = Q @ v1^T ===================
    for (int kc = 0; kc < 24; ++kc) {
        const int buf = kc % 3;
        mbar_wait(mb[buf], (kc / 3) & 1);
        __syncthreads();
        if (kc + 2 < 24 && tid == 0) {
            const int nb = (kc + 2) % 3;
            mbar_expect_tx(mb[nb], BUF_B);
            bulk_cp(sBu + nb * BUF_B, v1src + (size_t)(kc + 2) * BUF_B, BUF_B, mb[nb]);
        }
        uint32_t a[2][4];
#pragma unroll
        for (int ma = 0; ma < 2; ++ma)
            ldm4(a[ma], aBase + (ma * 16 * QS + kc * 16) * 2);
        const uint32_t bb = bBase1 + buf * BUF_B + wc * 96 * 48;
        uint32_t bfr[2][4];
        ldm4(bfr[0], bb);
#pragma unroll
        for (int nbx = 0; nbx < 6; ++nbx) {
            if (nbx < 5) ldm4(bfr[(nbx + 1) & 1], bb + (nbx + 1) * 16 * 48);
            const uint32_t* bc = bfr[nbx & 1];
#pragma unroll
            for (int ma = 0; ma < 2; ++ma) {
                mma16816(acc[ma][2 * nbx], a[ma], bc[0], bc[1]);
                mma16816(acc[ma][2 * nbx + 1], a[ma], bc[2], bc[3]);
            }
        }
    }

    // ---- kick off V chunks 0,1 (bufs 0,1 free; overlaps softmax) ----
    if (tid == 0) {
        mbar_expect_tx(mb[0], 16 * VS * 2);
        bulk_cp(sBu, vsrc, 16 * VS * 2, mb[0]);
        mbar_expect_tx(mb[1], 16 * VS * 2);
        bulk_cp(sBu + BUF_B, vsrc + (size_t)16 * VS * 2, 16 * VS * 2, mb[1]);
    }

    // ---- colsum -> smem ----
    if (tid < 384) {
        float s0 = 0.f;
#pragma unroll
        for (int p = 0; p < 6; ++p) s0 += __ldg(g_cs6 + ((size_t)i * 6 + p) * N + tid);
        cs_s[tid] = s0;
    }

    // =================== softmax: delta = e/s - 1/N (bf16 into sQ) ===================
    float rs[2][2] = {{0.f, 0.f}, {0.f, 0.f}};
#pragma unroll
    for (int ma = 0; ma < 2; ++ma)
#pragma unroll
        for (int na = 0; na < 12; ++na) {
            float* d = acc[ma][na];
            d[0] = __expf(d[0] * SCALE_INV);
            d[1] = __expf(d[1] * SCALE_INV);
            d[2] = __expf(d[2] * SCALE_INV);
            d[3] = __expf(d[3] * SCALE_INV);
            rs[ma][0] += d[0] + d[1];
            rs[ma][1] += d[2] + d[3];
        }
#pragma unroll
    for (int ma = 0; ma < 2; ++ma)
#pragma unroll
        for (int h = 0; h < 2; ++h) {
            rs[ma][h] += __shfl_xor_sync(0xffffffffu, rs[ma][h], 1);
            rs[ma][h] += __shfl_xor_sync(0xffffffffu, rs[ma][h], 2);
        }
    if ((lane & 3) == 0) {
#pragma unroll
        for (int ma = 0; ma < 2; ++ma)
#pragma unroll
            for (int h = 0; h < 2; ++h)
                srow[wc * 128 + wr * 32 + ma * 16 + h * 8 + (lane >> 2)] = rs[ma][h];
    }
    __syncthreads();
    float invs[2][2];
#pragma unroll
    for (int ma = 0; ma < 2; ++ma)
#pragma unroll
        for (int h = 0; h < 2; ++h) {
            int r = wr * 32 + ma * 16 + h * 8 + (lane >> 2);
            invs[ma][h] = 1.0f / (srow[r] + srow[128 + r] + srow[256 + r] + srow[384 + r]);
        }
#pragma unroll
    for (int ma = 0; ma < 2; ++ma)
#pragma unroll
        for (int na = 0; na < 12; ++na) {
            int r = wr * 32 + ma * 16 + (lane >> 2);
            int c = wc * 96 + (na >> 1) * 16 + (na & 1) * 8 + (lane & 3) * 2;
            float* d = acc[ma][na];
            *reinterpret_cast<uint32_t*>(sQ + r * QS + c) =
                bf2_pack(d[0] * invs[ma][0] - INV_N, d[1] * invs[ma][0] - INV_N);
            *reinterpret_cast<uint32_t*>(sQ + (r + 8) * QS + c) =
                bf2_pack(d[2] * invs[ma][1] - INV_N, d[3] * invs[ma][1] - INV_N);
        }
    __syncthreads();

    // =================== GEMM2: corr = delta @ V ===================
#pragma unroll
    for (int ma = 0; ma < 2; ++ma)
#pragma unroll
        for (int na = 0; na < 12; ++na)
#pragma unroll
            for (int r = 0; r < 4; ++r) acc[ma][na][r] = 0.0f;

    for (int nc = 0; nc < 24; ++nc) {
        const int buf = nc % 3;
        mbar_wait(mb[buf], (nc / 3) & 1);
        __syncthreads();
        if (nc + 2 < 24 && tid == 0) {
            const int nb = (nc + 2) % 3;
            mbar_expect_tx(mb[nb], 16 * VS * 2);
            bulk_cp(sBu + nb * BUF_B, vsrc + (size_t)(nc + 2) * 16 * VS * 2,
                    16 * VS * 2, mb[nb]);
        }
        uint32_t a[2][4];
#pragma unroll
        for (int ma = 0; ma < 2; ++ma)
            ldm4(a[ma], aBase + (ma * 16 * QS + nc * 16) * 2);
        const uint32_t bb = bBase2 + buf * BUF_B + wc * 96 * 2;
        uint32_t bfr[2][4];
        ldm4t(bfr[0], bb);
#pragma unroll
        for (int nbx = 0; nbx < 6; ++nbx) {
            if (nbx < 5) ldm4t(bfr[(nbx + 1) & 1], bb + (nbx + 1) * 16 * 2);
            const uint32_t* bc = bfr[nbx & 1];
#pragma unroll
            for (int ma = 0; ma < 2; ++ma) {
                mma16816(acc[ma][2 * nbx], a[ma], bc[0], bc[1]);
                mma16816(acc[ma][2 * nbx + 1], a[ma], bc[2], bc[3]);
            }
        }
    }

    // =================== epilogue: out = corr + colsum/384 ===================
#pragma unroll
    for (int ma = 0; ma < 2; ++ma)
#pragma unroll
        for (int nbx = 0; nbx < 6; ++nbx)
#pragma unroll
            for (int ct = 0; ct < 2; ++ct) {
                int na = nbx * 2 + ct;
                int r = j0 + wr * 32 + ma * 16 + (lane >> 2);
                int c = wc * 96 + nbx * 16 + ct * 8 + (lane & 3) * 2;
                float cs0 = cs_s[c] * INV_N;
                float cs1 = cs_s[c + 1] * INV_N;
                float* d = acc[ma][na];
                float2 o0 = make_float2(d[0] + cs0, d[1] + cs1);
                float2 o1 = make_float2(d[2] + cs0, d[3] + cs1);
                *reinterpret_cast<float2*>(out + ((size_t)i * N + r) * N + c) = o0;
                *reinterpret_cast<float2*>(out + ((size_t)i * N + r + 8) * N + c) = o1;
            }
}

// ---------------------------------------------------------------------------
extern "C" void kernel_launch(void* const* d_in, const int* in_sizes, int n_in,
                              void* d_out, int out_size) {
    const float* x1 = (const float*)d_in[0];
    const float* x2 = (const float*)d_in[1];
    const float* W  = (const float*)d_in[2];
    const float* b  = (const float*)d_in[3];
    float* out = (float*)d_out;
    (void)in_sizes; (void)n_in; (void)out_size;

    {
        cudaFuncSetAttribute(prep_kernel, cudaFuncAttributeMaxDynamicSharedMemorySize, SMEM_PREP);
        dim3 g(6, 386);
        prep_kernel<<<g, 256, SMEM_PREP>>>(x1, W, b, x2);
    }
    {
        cudaFuncSetAttribute(attn_kernel, cudaFuncAttributeMaxDynamicSharedMemorySize, SMEM_ATTN);
        dim3 g(3, 384);
        attn_kernel<<<g, 512, SMEM_ATTN>>>(out);
    }
}

// round 16
// speedup vs baseline: 2.2265x; 1.0474x over previous
#include <cuda_runtime.h>
#include <cuda_bf16.h>
#include <cstdint>

// out[i] = softmax((x2[i] @ v1^T)/1000) @ x2[i],  v1 = x1@W.T + b,  N=384.
// P = 1/384 + delta  ->  out = colsum(x2[i])/384 + delta @ x2[i].
// GEMMs: mma.sync m16n8k16 bf16 (R15 geometry).
// R16: prep reduced to linear-only (144 blocks). attn CTAs convert their own
//      128 x2 rows (fp32->bf16) into sQ + the shared g_xp image + fp32 colsum
//      partial, publish via threadfence+atomic flag; GEMM2 spins for siblings.

constexpr int N = 384;
constexpr float SCALE_INV = 1.0f / 1000.0f;
constexpr float INV_N = 1.0f / 384.0f;

constexpr int QS = 392;   // row stride (halves): 384 + 8 pad (sQ and g_xp)
constexpr int BS = 24;    // GEMM1 B row stride (halves): 16 + 8 pad (g_v1p)
constexpr int VS = 392;   // GEMM2 B row stride (halves) (= g_xp row stride)

constexpr int SQ_BYTES = 128 * QS * 2;        // 100352
constexpr int BUF_B    = 18432;               // v1 chunk 18432B; V chunk 12544B fits
constexpr int OFF_BUF  = SQ_BYTES;
constexpr int OFF_SROW = OFF_BUF + 3 * BUF_B;            // 155648
constexpr int OFF_CS   = OFF_SROW + 512 * 4;             // 157696
constexpr int OFF_RED  = OFF_CS + 384 * 4;               // 159232
constexpr int SMEM_ATTN = OFF_RED + 384 * 16;            // 165376

__device__ __align__(1024) __nv_bfloat16 g_xp[(size_t)N * N * QS];   // x2 bf16 image, 784B rows
__device__ __align__(1024) __nv_bfloat16 g_v1p[24 * N * BS];         // v1 K16-chunks, 48B rows
__device__ float g_cs3[(size_t)N * 3 * N];                           // per-CTA colsum partials
__device__ int g_flag[N];                                            // convert-done counters

// ---------------------------------------------------------------------------
__device__ __forceinline__ uint32_t smem_u32(const void* p) {
    uint32_t a;
    asm("{ .reg .u64 t; cvta.to.shared.u64 t, %1; cvt.u32.u64 %0, t; }" : "=r"(a) : "l"(p));
    return a;
}
__device__ __forceinline__ void ldm4(uint32_t* r, uint32_t addr) {
    asm volatile("ldmatrix.sync.aligned.m8n8.x4.shared.b16 {%0,%1,%2,%3},[%4];"
                 : "=r"(r[0]), "=r"(r[1]), "=r"(r[2]), "=r"(r[3]) : "r"(addr));
}
__device__ __forceinline__ void ldm4t(uint32_t* r, uint32_t addr) {
    asm volatile("ldmatrix.sync.aligned.m8n8.x4.trans.shared.b16 {%0,%1,%2,%3},[%4];"
                 : "=r"(r[0]), "=r"(r[1]), "=r"(r[2]), "=r"(r[3]) : "r"(addr));
}
__device__ __forceinline__ void mma16816(float* d, const uint32_t* a, uint32_t b0, uint32_t b1) {
    asm volatile("mma.sync.aligned.m16n8k16.row.col.f32.bf16.bf16.f32 "
                 "{%0,%1,%2,%3},{%4,%5,%6,%7},{%8,%9},{%0,%1,%2,%3};"
                 : "+f"(d[0]), "+f"(d[1]), "+f"(d[2]), "+f"(d[3])
                 : "r"(a[0]), "r"(a[1]), "r"(a[2]), "r"(a[3]), "r"(b0), "r"(b1));
}
__device__ __forceinline__ uint32_t bf2_pack(float a, float b) {
    __nv_bfloat162 h = __floats2bfloat162_rn(a, b);
    return *reinterpret_cast<uint32_t*>(&h);
}
__device__ __forceinline__ void bulk_cp(uint32_t dst, const void* src, uint32_t bytes,
                                        uint32_t mbar) {
    asm volatile("cp.async.bulk.shared::cluster.global.mbarrier::complete_tx::bytes "
                 "[%0], [%1], %2, [%3];"
                 :: "r"(dst), "l"(src), "r"(bytes), "r"(mbar) : "memory");
}
__device__ __forceinline__ void mbar_init(uint32_t mb, uint32_t cnt) {
    asm volatile("mbarrier.init.shared.b64 [%0], %1;" :: "r"(mb), "r"(cnt) : "memory");
}
__device__ __forceinline__ void mbar_expect_tx(uint32_t mb, uint32_t bytes) {
    asm volatile("mbarrier.arrive.expect_tx.shared.b64 _, [%0], %1;"
                 :: "r"(mb), "r"(bytes) : "memory");
}
__device__ __forceinline__ void mbar_wait(uint32_t mb, uint32_t parity) {
    asm volatile(
        "{\n .reg .pred P;\n"
        "W_%=:\n mbarrier.try_wait.parity.shared.b64 P, [%0], %1;\n"
        " @P bra.uni D_%=;\n bra.uni W_%=;\nD_%=:\n}"
        :: "r"(mb), "r"(parity) : "memory");
}

// ---------------------------------------------------------------------------
// linear kernel: grid (12,12), 256 threads, 32x32 output tile, K=384.
// Also zeroes g_flag (replay-safe reset before attn).
// ---------------------------------------------------------------------------
__global__ __launch_bounds__(256) void linear_kernel(const float* __restrict__ x1,
                                                     const float* __restrict__ W,
                                                     const float* __restrict__ b) {
    __shared__ float sX[32][33], sW[32][33];
    const int tid = threadIdx.x;
    const int n0 = blockIdx.y * 32, k0 = blockIdx.x * 32;
    if (blockIdx.y == 0 && tid < 32) g_flag[blockIdx.x * 32 + tid] = 0;

    const int ty = tid >> 4, tx = tid & 15;
    float acc[2][2] = {{0.f, 0.f}, {0.f, 0.f}};
    for (int m0 = 0; m0 < N; m0 += 32) {
        const int r = tid >> 3, c4 = (tid & 7) * 4;
        float4 fx = *reinterpret_cast<const float4*>(x1 + (size_t)(n0 + r) * N + m0 + c4);
        sX[r][c4] = fx.x; sX[r][c4 + 1] = fx.y; sX[r][c4 + 2] = fx.z; sX[r][c4 + 3] = fx.w;
        float4 fw = *reinterpret_cast<const float4*>(W + (size_t)(k0 + r) * N + m0 + c4);
        sW[r][c4] = fw.x; sW[r][c4 + 1] = fw.y; sW[r][c4 + 2] = fw.z; sW[r][c4 + 3] = fw.w;
        __syncthreads();
#pragma unroll
        for (int mm = 0; mm < 32; ++mm) {
            float a0 = sX[ty * 2][mm], a1 = sX[ty * 2 + 1][mm];
            float b0 = sW[tx * 2][mm], b1 = sW[tx * 2 + 1][mm];
            acc[0][0] += a0 * b0; acc[0][1] += a0 * b1;
            acc[1][0] += a1 * b0; acc[1][1] += a1 * b1;
        }
        __syncthreads();
    }
#pragma unroll
    for (int r2 = 0; r2 < 2; ++r2)
#pragma unroll
        for (int k2 = 0; k2 < 2; ++k2) {
            int n = n0 + ty * 2 + r2, k = k0 + tx * 2 + k2;
            g_v1p[((size_t)(k >> 4) * N + n) * BS + (k & 15)] =
                __float2bfloat16(acc[r2][k2] + __ldg(b + k));
        }
}

// ---------------------------------------------------------------------------
// Fused convert + attention: 512 threads, 16 warps = 4 row x 4 col groups.
// ---------------------------------------------------------------------------
__global__ __launch_bounds__(512, 1)
void attn_kernel(const float* __restrict__ x2, float* __restrict__ out) {
    extern __shared__ char smem[];
    __shared__ __align__(8) uint64_t s_mbar[3];
    __nv_bfloat16* sQ = reinterpret_cast<__nv_bfloat16*>(smem);
    float* srow = reinterpret_cast<float*>(smem + OFF_SROW);
    float* cs_s = reinterpret_cast<float*>(smem + OFF_CS);
    float4* red4 = reinterpret_cast<float4*>(smem + OFF_RED);

    const int tid = threadIdx.x;
    const int lane = tid & 31;
    const int warp = tid >> 5;
    const int wr = warp & 3;       // rows wr*32..+32
    const int wc = warp >> 2;      // cols wc*96..+96
    const int i = blockIdx.y;
    const int jb = blockIdx.x;
    const int j0 = jb * 128;

    const uint32_t sQu = smem_u32(smem);
    const uint32_t sBu = sQu + OFF_BUF;
    uint32_t mb[3];
#pragma unroll
    for (int q = 0; q < 3; ++q) mb[q] = smem_u32(&s_mbar[q]);

    const int rowA = (lane & 7) + ((lane >> 3) & 1) * 8;
    const int colA = (lane >> 4) * 8;
    const uint32_t aBase = sQu + ((wr * 32 + rowA) * QS + colA) * 2;

    const int rowB = (lane & 7) + ((lane >> 4) & 1) * 8;
    const int colB = ((lane >> 3) & 1) * 8;
    const uint32_t bBase1 = sBu + (rowB * BS + colB) * 2;

    const int rowV = (lane & 7) + ((lane >> 3) & 1) * 8;
    const int colV = ((lane >> 4) & 1) * 8;
    const uint32_t bBase2 = sBu + (rowV * VS + colV) * 2;

    // ---- init mbarriers, kick off v1 chunks 0,1 ----
    if (tid == 0) {
#pragma unroll
        for (int q = 0; q < 3; ++q) mbar_init(mb[q], 1);
    }
    __syncthreads();
    const char* v1src = reinterpret_cast<const char*>(g_v1p);
    if (tid == 0) {
        mbar_expect_tx(mb[0], BUF_B);
        bulk_cp(sBu, v1src, BUF_B, mb[0]);
        mbar_expect_tx(mb[1], BUF_B);
        bulk_cp(sBu + BUF_B, v1src + BUF_B, BUF_B, mb[1]);
    }

    // ---- convert own 128 rows: fp32 x2 -> sQ (smem) + g_xp (image) + colsum ----
    {
        const float* xsrc = x2 + ((size_t)i * N + j0) * N;
        __nv_bfloat16* img = g_xp + ((size_t)i * N + j0) * QS;
        if (tid < 384) {
            const int c4 = tid % 96, rh = tid / 96;
            float4 cs = make_float4(0.f, 0.f, 0.f, 0.f);
#pragma unroll
            for (int q = 0; q < 32; ++q) {
                int r = rh + 4 * q;
                float4 f = __ldg(reinterpret_cast<const float4*>(xsrc + (size_t)r * N) + c4);
                cs.x += f.x; cs.y += f.y; cs.z += f.z; cs.w += f.w;
                uint2 u = make_uint2(bf2_pack(f.x, f.y), bf2_pack(f.z, f.w));
                *reinterpret_cast<uint2*>(img + (size_t)r * QS + c4 * 4) = u;
                *reinterpret_cast<uint2*>(sQ + r * QS + c4 * 4) = u;
            }
            red4[tid] = cs;
        }
        __syncthreads();
        if (tid < 96) {
            float4 a = red4[tid], b2 = red4[tid + 96], c2 = red4[tid + 192], d2 = red4[tid + 288];
            float4 s = make_float4(a.x + b2.x + c2.x + d2.x, a.y + b2.y + c2.y + d2.y,
                                   a.z + b2.z + c2.z + d2.z, a.w + b2.w + c2.w + d2.w);
            *reinterpret_cast<float4*>(g_cs3 + ((size_t)(i * 3 + jb)) * N + tid * 4) = s;
        }
        __threadfence();
        __syncthreads();
        if (tid == 0) atomicAdd(&g_flag[i], 1);
    }

    float acc[2][12][4];
#pragma unroll
    for (int ma = 0; ma < 2; ++ma)
#pragma unroll
        for (int na = 0; na < 12; ++na)
#pragma unroll
            for (int r = 0; r < 4; ++r) acc[ma][na][r] = 0.0f;

    // =================== GEMM1: S = Q @ v1^T ===================
    for (int kc = 0; kc < 24; ++kc) {
        const int buf = kc % 3;
        mbar_wait(mb[buf], (kc / 3) & 1);
        __syncthreads();
        if (kc + 2 < 24 && tid == 0) {
            const int nb = (kc + 2) % 3;
            mbar_expect_tx(mb[nb], BUF_B);
            bulk_cp(sBu + nb * BUF_B, v1src + (size_t)(kc + 2) * BUF_B, BUF_B, mb[nb]);
        }
        uint32_t a[2][4];
#pragma unroll
        for (int ma = 0; ma < 2; ++ma)
            ldm4(a[ma], aBase + (ma * 16 * QS + kc * 16) * 2);
        const uint32_t bb = bBase1 + buf * BUF_B + wc * 96 * 48;
        uint32_t bfr[2][4];
        ldm4(bfr[0], bb);
#pragma unroll
        for (int nbx = 0; nbx < 6; ++nbx) {
            if (nbx < 5) ldm4(bfr[(nbx + 1) & 1], bb + (nbx + 1) * 16 * 48);
            const uint32_t* bc = bfr[nbx & 1];
#pragma unroll
            for (int ma = 0; ma < 2; ++ma) {
                mma16816(acc[ma][2 * nbx], a[ma], bc[0], bc[1]);
                mma16816(acc[ma][2 * nbx + 1], a[ma], bc[2], bc[3]);
            }
        }
    }

    // =================== softmax: delta = e/s - 1/N (bf16 into sQ) ===================
    float rs[2][2] = {{0.f, 0.f}, {0.f, 0.f}};
#pragma unroll
    for (int ma = 0; ma < 2; ++ma)
#pragma unroll
        for (int na = 0; na < 12; ++na) {
            float* d = acc[ma][na];
            d[0] = __expf(d[0] * SCALE_INV);
            d[1] = __expf(d[1] * SCALE_INV);
            d[2] = __expf(d[2] * SCALE_INV);
            d[3] = __expf(d[3] * SCALE_INV);
            rs[ma][0] += d[0] + d[1];
            rs[ma][1] += d[2] + d[3];
        }
#pragma unroll
    for (int ma = 0; ma < 2; ++ma)
#pragma unroll
        for (int h = 0; h < 2; ++h) {
            rs[ma][h] += __shfl_xor_sync(0xffffffffu, rs[ma][h], 1);
            rs[ma][h] += __shfl_xor_sync(0xffffffffu, rs[ma][h], 2);
        }
    if ((lane & 3) == 0) {
#pragma unroll
        for (int ma = 0; ma < 2; ++ma)
#pragma unroll
            for (int h = 0; h < 2; ++h)
                srow[wc * 128 + wr * 32 + ma * 16 + h * 8 + (lane >> 2)] = rs[ma][h];
    }
    __syncthreads();
    float invs[2][2];
#pragma unroll
    for (int ma = 0; ma < 2; ++ma)
#pragma unroll
        for (int h = 0; h < 2; ++h) {
            int r = wr * 32 + ma * 16 + h * 8 + (lane >> 2);
            invs[ma][h] = 1.0f / (srow[r] + srow[128 + r] + srow[256 + r] + srow[384 + r]);
        }
#pragma unroll
    for (int ma = 0; ma < 2; ++ma)
#pragma unroll
        for (int na = 0; na < 12; ++na) {
            int r = wr * 32 + ma * 16 + (lane >> 2);
            int c = wc * 96 + (na >> 1) * 16 + (na & 1) * 8 + (lane & 3) * 2;
            float* d = acc[ma][na];
            *reinterpret_cast<uint32_t*>(sQ + r * QS + c) =
                bf2_pack(d[0] * invs[ma][0] - INV_N, d[1] * invs[ma][0] - INV_N);
            *reinterpret_cast<uint32_t*>(sQ + (r + 8) * QS + c) =
                bf2_pack(d[2] * invs[ma][1] - INV_N, d[3] * invs[ma][1] - INV_N);
        }
    __syncthreads();

    // ---- wait for siblings' converts, then kick off V chunks 0,1 ----
    if (tid == 0) {
        while (atomicAdd(&g_flag[i], 0) < 3) {}
    }
    __syncthreads();
    const char* vsrc = reinterpret_cast<const char*>(g_xp + (size_t)i * N * QS);
    if (tid == 0) {
        mbar_expect_tx(mb[0], 16 * VS * 2);
        bulk_cp(sBu, vsrc, 16 * VS * 2, mb[0]);
        mbar_expect_tx(mb[1], 16 * VS * 2);
        bulk_cp(sBu + BUF_B, vsrc + (size_t)16 * VS * 2, 16 * VS * 2, mb[1]);
    }
    // colsum assembly (after flag: partials visible)
    if (tid < 384) {
        float s0 = 0.f;
#pragma unroll
        for (int p = 0; p < 3; ++p) s0 += __ldg(g_cs3 + ((size_t)(i * 3 + p)) * N + tid);
        cs_s[tid] = s0;
    }

    // =================== GEMM2: corr = delta @ V ===================
#pragma unroll
    for (int ma = 0; ma < 2; ++ma)
#pragma unroll
        for (int na = 0; na < 12; ++na)
#pragma unroll
            for (int r = 0; r < 4; ++r) acc[ma][na][r] = 0.0f;

    for (int nc = 0; nc < 24; ++nc) {
        const int buf = nc % 3;
        mbar_wait(mb[buf], (nc / 3) & 1);
        __syncthreads();
        if (nc + 2 < 24 && tid == 0) {
            const int nb = (nc + 2) % 3;
            mbar_expect_tx(mb[nb], 16 * VS * 2);
            bulk_cp(sBu + nb * BUF_B, vsrc + (size_t)(nc + 2) * 16 * VS * 2,
                    16 * VS * 2, mb[nb]);
        }
        uint32_t a[2][4];
#pragma unroll
        for (int ma = 0; ma < 2; ++ma)
            ldm4(a[ma], aBase + (ma * 16 * QS + nc * 16) * 2);
        const uint32_t bb = bBase2 + buf * BUF_B + wc * 96 * 2;
        uint32_t bfr[2][4];
        ldm4t(bfr[0], bb);
#pragma unroll
        for (int nbx = 0; nbx < 6; ++nbx) {
            if (nbx < 5) ldm4t(bfr[(nbx + 1) & 1], bb + (nbx + 1) * 16 * 2);
            const uint32_t* bc = bfr[nbx & 1];
#pragma unroll
            for (int ma = 0; ma < 2; ++ma) {
                mma16816(acc[ma][2 * nbx], a[ma], bc[0], bc[1]);
                mma16816(acc[ma][2 * nbx + 1], a[ma], bc[2], bc[3]);
            }
        }
    }

    // =================== epilogue: out = corr + colsum/384 ===================
#pragma unroll
    for (int ma = 0; ma < 2; ++ma)
#pragma unroll
        for (int nbx = 0; nbx < 6; ++nbx)
#pragma unroll
            for (int ct = 0; ct < 2; ++ct) {
                int na = nbx * 2 + ct;
                int r = j0 + wr * 32 + ma * 16 + (lane >> 2);
                int c = wc * 96 + nbx * 16 + ct * 8 + (lane & 3) * 2;
                float cs0 = cs_s[c] * INV_N;
                float cs1 = cs_s[c + 1] * INV_N;
                float* d = acc[ma][na];
                float2 o0 = make_float2(d[0] + cs0, d[1] + cs1);
                float2 o1 = make_float2(d[2] + cs0, d[3] + cs1);
                *reinterpret_cast<float2*>(out + ((size_t)i * N + r) * N + c) = o0;
                *reinterpret_cast<float2*>(out + ((size_t)i * N + r + 8) * N + c) = o1;
            }
}

// ---------------------------------------------------------------------------
extern "C" void kernel_launch(void* const* d_in, const int* in_sizes, int n_in,
                              void* d_out, int out_size) {
    const float* x1 = (const float*)d_in[0];
    const float* x2 = (const float*)d_in[1];
    const float* W  = (const float*)d_in[2];
    const float* b  = (const float*)d_in[3];
    float* out = (float*)d_out;
    (void)in_sizes; (void)n_in; (void)out_size;

    {
        dim3 g(12, 12);
        linear_kernel<<<g, 256>>>(x1, W, b);
    }
    {
        cudaFuncSetAttribute(attn_kernel, cudaFuncAttributeMaxDynamicSharedMemorySize, SMEM_ATTN);
        dim3 g(3, 384);
        attn_kernel<<<g, 512, SMEM_ATTN>>>(x2, out);
    }
}